// round 8
// baseline (speedup 1.0000x reference)
#include <cuda_runtime.h>
#include <cuda_bf16.h>
#include <math.h>
#include <stdint.h>

// ---------------------------------------------------------------------------
// HybridTTLayer via mma.sync bf16 tensor cores (plain sm_100 target — no
// tcgen05 available). fp32 emulated as bf16 hi+lo split, 3-product MMA.
//   LN -> dense(gelu)/gate -> TT(1024->4096, dense W_tt) -> LN -> dense/gate
// R7: CTA tile 128x256, warp tile 64x64, BK=32, 3-stage cp.async pipeline.
// ---------------------------------------------------------------------------

#define NTOK   4096
#define DIN    1024
#define DOUT   4096

#define OP_NONE 0
#define OP_GELU 1
#define OP_GATE 2

// GEMM tiling
#define BM 128
#define BN 256
#define BK 32
#define STAGES 3
#define ROWB 80                        // smem bytes per 32-bf16 row (padded)
#define OFF_AH 0
#define OFF_AL 10240                   // 128*80
#define OFF_BH 20480
#define OFF_BL 40960                   // BH + 256*80
#define STAGE_BYTES 61440
#define GEMM_SMEM (STAGES * STAGE_BYTES)   // 184320

// ------------------------- scratch (static device memory) ------------------
__device__ float g_h1 [NTOK * DIN];
__device__ float g_t  [NTOK * DOUT];
__device__ float g_h2 [NTOK * DOUT];
__device__ float g_a01[8 * 8 * 8 * 16 * 16];
__device__ __nv_bfloat16 g_xH   [NTOK * DIN],  g_xL   [NTOK * DIN];
__device__ __nv_bfloat16 g_ln1H [NTOK * DIN],  g_ln1L [NTOK * DIN];
__device__ __nv_bfloat16 g_hpreH[NTOK * DIN],  g_hpreL[NTOK * DIN];
__device__ __nv_bfloat16 g_tH   [NTOK * DOUT], g_tL   [NTOK * DOUT];
__device__ __nv_bfloat16 g_ln2H [NTOK * DOUT], g_ln2L [NTOK * DOUT];
__device__ __nv_bfloat16 g_preDwTH [DIN * DIN],   g_preDwTL [DIN * DIN];
__device__ __nv_bfloat16 g_preGwTH [DIN * DIN],   g_preGwTL [DIN * DIN];
__device__ __nv_bfloat16 g_wttTH   [DOUT * DIN],  g_wttTL   [DOUT * DIN];
__device__ __nv_bfloat16 g_postDwTH[DOUT * DOUT], g_postDwTL[DOUT * DOUT];
__device__ __nv_bfloat16 g_postGwTH[DOUT * DOUT], g_postGwTL[DOUT * DOUT];

// ------------------------- helpers -----------------------------------------
__device__ __forceinline__ uint32_t smem_u32(const void* p) {
    uint32_t a;
    asm("{ .reg .u64 t; cvta.to.shared.u64 t, %1; cvt.u32.u64 %0, t; }"
        : "=r"(a) : "l"(p));
    return a;
}
__device__ __forceinline__ void cp16(uint32_t s, const void* g) {
    asm volatile("cp.async.cg.shared.global [%0], [%1], 16;" :: "r"(s), "l"(g));
}
#define CP_COMMIT() asm volatile("cp.async.commit_group;")
#define CP_WAIT1()  asm volatile("cp.async.wait_group 1;")
#define CP_WAIT0()  asm volatile("cp.async.wait_group 0;")

__device__ __forceinline__ void ldmx4(uint32_t* r, uint32_t a) {
    asm volatile("ldmatrix.sync.aligned.m8n8.x4.shared.b16 {%0,%1,%2,%3}, [%4];"
        : "=r"(r[0]), "=r"(r[1]), "=r"(r[2]), "=r"(r[3]) : "r"(a));
}
__device__ __forceinline__ void mma_bf16(float* d, const uint32_t* a, const uint32_t* b) {
    asm volatile("mma.sync.aligned.m16n8k16.row.col.f32.bf16.bf16.f32 "
        "{%0,%1,%2,%3}, {%4,%5,%6,%7}, {%8,%9}, {%0,%1,%2,%3};"
        : "+f"(d[0]), "+f"(d[1]), "+f"(d[2]), "+f"(d[3])
        : "r"(a[0]), "r"(a[1]), "r"(a[2]), "r"(a[3]), "r"(b[0]), "r"(b[1]));
}
__device__ __forceinline__ float gelu_exact(float v) {
    return 0.5f * v * (1.0f + erff(v * 0.70710678118654752f));
}
__device__ __forceinline__ float sigmoidf_(float v) {
    return 1.0f / (1.0f + __expf(-v));
}
__device__ __forceinline__ void split_bf16(float v, __nv_bfloat16& h, __nv_bfloat16& l) {
    h = __float2bfloat16_rn(v);
    l = __float2bfloat16_rn(v - __bfloat162float(h));
}

// ------------------------- layernorm (emits bf16 hi/lo) ----------------------
template <int EPT, bool SPLIT_IN>
__global__ __launch_bounds__(256) void layernorm_split_kernel(
    const float* __restrict__ in, const float* __restrict__ gamma,
    const float* __restrict__ beta,
    __nv_bfloat16* __restrict__ oH, __nv_bfloat16* __restrict__ oL,
    __nv_bfloat16* __restrict__ iH, __nv_bfloat16* __restrict__ iL, int D)
{
    const int row = blockIdx.x;
    const int tid = threadIdx.x;
    const float* rp = in + (size_t)row * D;

    float v[EPT];
    float s = 0.f;
#pragma unroll
    for (int e = 0; e < EPT; e++) { v[e] = rp[tid + e * 256]; s += v[e]; }

    __shared__ float red[8];
    __shared__ float sMean, sVar;
#pragma unroll
    for (int o = 16; o > 0; o >>= 1) s += __shfl_down_sync(0xffffffffu, s, o);
    if ((tid & 31) == 0) red[tid >> 5] = s;
    __syncthreads();
    if (tid < 8) {
        float w = red[tid];
#pragma unroll
        for (int o = 4; o > 0; o >>= 1) w += __shfl_down_sync(0xffu, w, o);
        if (tid == 0) sMean = w / (float)D;
    }
    __syncthreads();
    const float mean = sMean;

    float q = 0.f;
#pragma unroll
    for (int e = 0; e < EPT; e++) { float d = v[e] - mean; q += d * d; }
#pragma unroll
    for (int o = 16; o > 0; o >>= 1) q += __shfl_down_sync(0xffffffffu, q, o);
    if ((tid & 31) == 0) red[tid >> 5] = q;
    __syncthreads();
    if (tid < 8) {
        float w = red[tid];
#pragma unroll
        for (int o = 4; o > 0; o >>= 1) w += __shfl_down_sync(0xffu, w, o);
        if (tid == 0) sVar = w / (float)D;
    }
    __syncthreads();
    const float inv = rsqrtf(sVar + 1e-6f);

    const size_t rb = (size_t)row * D;
#pragma unroll
    for (int e = 0; e < EPT; e++) {
        int c = tid + e * 256;
        float o = (v[e] - mean) * inv * gamma[c] + beta[c];
        __nv_bfloat16 h, l;
        split_bf16(o, h, l);
        oH[rb + c] = h; oL[rb + c] = l;
        if (SPLIT_IN) {
            split_bf16(v[e], h, l);
            iH[rb + c] = h; iL[rb + c] = l;
        }
    }
}

// ------------------------- TT operator materialization ----------------------
__global__ __launch_bounds__(256) void build_a01_kernel(
    const float* __restrict__ c0, const float* __restrict__ c1,
    float* __restrict__ a01)
{
    int idx = blockIdx.x * 256 + threadIdx.x;   // 131072
    int s = idx & 15, y = (idx >> 4) & 15, b = (idx >> 8) & 7;
    int x = (idx >> 11) & 7, a = idx >> 14;
    float acc = 0.f;
#pragma unroll
    for (int r = 0; r < 16; r++)
        acc += c0[a * 128 + x * 16 + r] * c1[((r * 8 + b) * 16 + y) * 16 + s];
    a01[idx] = acc;
}

// wttT[out][in] as bf16 hi/lo; out = x*512+y*32+z; in = a*128+b*16+c
__global__ __launch_bounds__(256) void build_wttT_kernel(
    const float* __restrict__ a01, const float* __restrict__ c2,
    __nv_bfloat16* __restrict__ wH, __nv_bfloat16* __restrict__ wL)
{
    int idx = blockIdx.x * 256 + threadIdx.x;   // 4096*1024
    int in  = idx & 1023;
    int out = idx >> 10;
    int z = out & 31, y = (out >> 5) & 15, x = out >> 9;
    int c = in & 15,  b = (in >> 4) & 7,   a = in >> 7;
    const float* ap = a01 + (((a * 8 + x) * 8 + b) * 16 + y) * 16;
    float acc = 0.f;
#pragma unroll
    for (int s = 0; s < 16; s++)
        acc += ap[s] * c2[(s * 16 + c) * 32 + z];
    __nv_bfloat16 h, l;
    split_bf16(acc, h, l);
    wH[idx] = h; wL[idx] = l;
}

// ------------------------- weight transpose + split --------------------------
__global__ __launch_bounds__(256) void transpose_split_kernel(
    const float* __restrict__ in, __nv_bfloat16* __restrict__ oH,
    __nv_bfloat16* __restrict__ oL, int K, int N)
{
    __shared__ float tile[32][33];
    int n0 = blockIdx.x * 32, k0 = blockIdx.y * 32;
    int tx = threadIdx.x & 31, ty = threadIdx.x >> 5;
#pragma unroll
    for (int i = 0; i < 4; i++)
        tile[ty + i * 8][tx] = in[(size_t)(k0 + ty + i * 8) * N + n0 + tx];
    __syncthreads();
#pragma unroll
    for (int i = 0; i < 4; i++) {
        float v = tile[tx][ty + i * 8];
        __nv_bfloat16 h, l;
        split_bf16(v, h, l);
        size_t o = (size_t)(n0 + ty + i * 8) * K + k0 + tx;
        oH[o] = h; oL[o] = l;
    }
}

// ------------------------- mma.sync GEMM ------------------------------------
// C = A[M,K] @ Bt[N,K]^T with bf16 hi/lo 3-product emulation.
__device__ __forceinline__ void load_stage(
    uint32_t sbase,
    const __nv_bfloat16* __restrict__ Ah, const __nv_bfloat16* __restrict__ Al,
    const __nv_bfloat16* __restrict__ Bh, const __nv_bfloat16* __restrict__ Bl,
    int aRow0, int bRow0, int K, int k0, int tid)
{
    // A: 128 rows x 4 16B-cols = 512 ops / 256 threads = 2 each
#pragma unroll
    for (int i = 0; i < 2; i++) {
        int idx = tid + i * 256;
        int r = idx >> 2, c = idx & 3;
        uint32_t so = (uint32_t)(r * ROWB + c * 16);
        size_t ga = (size_t)(aRow0 + r) * K + k0 + c * 8;
        cp16(sbase + OFF_AH + so, Ah + ga);
        cp16(sbase + OFF_AL + so, Al + ga);
    }
    // B: 256 rows x 4 = 1024 ops / 256 threads = 4 each
#pragma unroll
    for (int i = 0; i < 4; i++) {
        int idx = tid + i * 256;
        int r = idx >> 2, c = idx & 3;
        uint32_t so = (uint32_t)(r * ROWB + c * 16);
        size_t gb = (size_t)(bRow0 + r) * K + k0 + c * 8;
        cp16(sbase + OFF_BH + so, Bh + gb);
        cp16(sbase + OFF_BL + so, Bl + gb);
    }
}

template <int OP>
__device__ __forceinline__ float epi_op(float acc, float b, float h, float r) {
    if (OP == OP_GELU) return gelu_exact(acc + b);
    if (OP == OP_GATE) { float g = sigmoidf_(acc + b); return g * h + (1.f - g) * r; }
    return acc;
}

template <int OP, bool WF32, bool WSPLIT>
__global__ __launch_bounds__(256, 1) void mma_gemm_kernel(
    const __nv_bfloat16* __restrict__ Ah, const __nv_bfloat16* __restrict__ Al,
    const __nv_bfloat16* __restrict__ Bh, const __nv_bfloat16* __restrict__ Bl,
    const float* __restrict__ bias, const float* __restrict__ Hm,
    const float* __restrict__ Rm,
    float* __restrict__ CF, __nv_bfloat16* __restrict__ CH,
    __nv_bfloat16* __restrict__ CL, int M, int N, int K)
{
    extern __shared__ char smem[];
    const uint32_t sm = smem_u32(smem);
    const int tid  = threadIdx.x;
    const int lane = tid & 31;
    const int wid  = tid >> 5;
    const int blockM = blockIdx.x * BM;   // x fastest over M: B slab reused in L2
    const int blockN = blockIdx.y * BN;
    const int wm = (wid >> 2) * 64;       // 2 warp rows
    const int wn = (wid & 3) * 64;        // 4 warp cols
    const int nk = K / BK;

    float acc[4][8][4];
#pragma unroll
    for (int i = 0; i < 4; i++)
#pragma unroll
        for (int j = 0; j < 8; j++)
#pragma unroll
            for (int e = 0; e < 4; e++) acc[i][j][e] = 0.f;

#pragma unroll
    for (int s = 0; s < STAGES - 1; s++) {
        load_stage(sm + s * STAGE_BYTES, Ah, Al, Bh, Bl, blockM, blockN, K, s * BK, tid);
        CP_COMMIT();
    }

    const uint32_t aRowOff = (uint32_t)((lane & 15) * ROWB);
    const uint32_t aColOff = (uint32_t)((lane >> 4) * 16);
    const uint32_t bRowOff = (uint32_t)((wn + (lane & 7) + ((lane >> 4) << 3)) * ROWB);
    const uint32_t bColOff = (uint32_t)(((lane >> 3) & 1) * 16);

    for (int t = 0; t < nk; t++) {
        CP_WAIT1();
        __syncthreads();
        const int pf = t + STAGES - 1;
        if (pf < nk)
            load_stage(sm + (pf % STAGES) * STAGE_BYTES, Ah, Al, Bh, Bl,
                       blockM, blockN, K, pf * BK, tid);
        CP_COMMIT();

        const uint32_t sb = sm + (t % STAGES) * STAGE_BYTES;
#pragma unroll
        for (int ks = 0; ks < 2; ks++) {
            uint32_t ah[4][4], al[4][4];
            const uint32_t abase = sb + ks * 32 + aColOff + aRowOff;
#pragma unroll
            for (int mt = 0; mt < 4; mt++) {
                ldmx4(ah[mt], abase + OFF_AH + (uint32_t)((wm + mt * 16) * ROWB));
                ldmx4(al[mt], abase + OFF_AL + (uint32_t)((wm + mt * 16) * ROWB));
            }
            const uint32_t bbase = sb + ks * 32 + bColOff + bRowOff;
#pragma unroll
            for (int g = 0; g < 4; g++) {
                uint32_t bh0[4], bl0[4];
                const uint32_t bg = bbase + (uint32_t)(g * 16 * ROWB);
                ldmx4(bh0, bg + OFF_BH);
                ldmx4(bl0, bg + OFF_BL);
#pragma unroll
                for (int mt = 0; mt < 4; mt++) {
                    mma_bf16(acc[mt][2 * g],     ah[mt], bh0 + 0);
                    mma_bf16(acc[mt][2 * g],     ah[mt], bl0 + 0);
                    mma_bf16(acc[mt][2 * g],     al[mt], bh0 + 0);
                    mma_bf16(acc[mt][2 * g + 1], ah[mt], bh0 + 2);
                    mma_bf16(acc[mt][2 * g + 1], ah[mt], bl0 + 2);
                    mma_bf16(acc[mt][2 * g + 1], al[mt], bh0 + 2);
                }
            }
        }
    }
    CP_WAIT0();

    // ---------------- epilogue ----------------
    const int r0 = lane >> 2;
    const int c0 = (lane & 3) * 2;
#pragma unroll
    for (int mt = 0; mt < 4; mt++) {
#pragma unroll
        for (int half = 0; half < 2; half++) {
            const int m = blockM + wm + mt * 16 + r0 + half * 8;
            const size_t base = (size_t)m * N;
#pragma unroll
            for (int nt = 0; nt < 8; nt++) {
                const int n = blockN + wn + nt * 8 + c0;
                float v0 = acc[mt][nt][half * 2 + 0];
                float v1 = acc[mt][nt][half * 2 + 1];
                float b0 = 0.f, b1 = 0.f, h0 = 0.f, h1 = 0.f, rr0 = 0.f, rr1 = 0.f;
                if (OP != OP_NONE) { b0 = bias[n]; b1 = bias[n + 1]; }
                if (OP == OP_GATE) {
                    float2 hh = *(const float2*)(Hm + base + n);
                    float2 rr = *(const float2*)(Rm + base + n);
                    h0 = hh.x; h1 = hh.y; rr0 = rr.x; rr1 = rr.y;
                }
                v0 = epi_op<OP>(v0, b0, h0, rr0);
                v1 = epi_op<OP>(v1, b1, h1, rr1);
                if (WF32) *(float2*)(CF + base + n) = make_float2(v0, v1);
                if (WSPLIT) {
                    __nv_bfloat16 hA, lA, hB, lB;
                    split_bf16(v0, hA, lA);
                    split_bf16(v1, hB, lB);
                    __nv_bfloat162 ph; ph.x = hA; ph.y = hB;
                    __nv_bfloat162 pl; pl.x = lA; pl.y = lB;
                    *(__nv_bfloat162*)(CH + base + n) = ph;
                    *(__nv_bfloat162*)(CL + base + n) = pl;
                }
            }
        }
    }
}

// ------------------------- launch ------------------------------------------
extern "C" void kernel_launch(void* const* d_in, const int* in_sizes, int n_in,
                              void* d_out, int out_size)
{
    const float* x      = (const float*)d_in[0];
    const float* preG   = (const float*)d_in[1];
    const float* preB   = (const float*)d_in[2];
    const float* preDw  = (const float*)d_in[3];
    const float* preDb  = (const float*)d_in[4];
    const float* preGw  = (const float*)d_in[5];
    const float* preGb  = (const float*)d_in[6];
    const float* core0  = (const float*)d_in[7];
    const float* core1  = (const float*)d_in[8];
    const float* core2  = (const float*)d_in[9];
    const float* postG  = (const float*)d_in[10];
    const float* postB  = (const float*)d_in[11];
    const float* postDw = (const float*)d_in[12];
    const float* postDb = (const float*)d_in[13];
    const float* postGw = (const float*)d_in[14];
    const float* postGb = (const float*)d_in[15];
    float* out = (float*)d_out;

    float *h1, *t, *h2, *a01;
    cudaGetSymbolAddress((void**)&h1,  g_h1);
    cudaGetSymbolAddress((void**)&t,   g_t);
    cudaGetSymbolAddress((void**)&h2,  g_h2);
    cudaGetSymbolAddress((void**)&a01, g_a01);

    __nv_bfloat16 *xH, *xL, *ln1H, *ln1L, *hpreH, *hpreL, *tH, *tL, *ln2H, *ln2L;
    __nv_bfloat16 *preDwTH, *preDwTL, *preGwTH, *preGwTL;
    __nv_bfloat16 *wttTH, *wttTL, *postDwTH, *postDwTL, *postGwTH, *postGwTL;
    cudaGetSymbolAddress((void**)&xH,    g_xH);    cudaGetSymbolAddress((void**)&xL,    g_xL);
    cudaGetSymbolAddress((void**)&ln1H,  g_ln1H);  cudaGetSymbolAddress((void**)&ln1L,  g_ln1L);
    cudaGetSymbolAddress((void**)&hpreH, g_hpreH); cudaGetSymbolAddress((void**)&hpreL, g_hpreL);
    cudaGetSymbolAddress((void**)&tH,    g_tH);    cudaGetSymbolAddress((void**)&tL,    g_tL);
    cudaGetSymbolAddress((void**)&ln2H,  g_ln2H);  cudaGetSymbolAddress((void**)&ln2L,  g_ln2L);
    cudaGetSymbolAddress((void**)&preDwTH,  g_preDwTH);  cudaGetSymbolAddress((void**)&preDwTL,  g_preDwTL);
    cudaGetSymbolAddress((void**)&preGwTH,  g_preGwTH);  cudaGetSymbolAddress((void**)&preGwTL,  g_preGwTL);
    cudaGetSymbolAddress((void**)&wttTH,    g_wttTH);    cudaGetSymbolAddress((void**)&wttTL,    g_wttTL);
    cudaGetSymbolAddress((void**)&postDwTH, g_postDwTH); cudaGetSymbolAddress((void**)&postDwTL, g_postDwTL);
    cudaGetSymbolAddress((void**)&postGwTH, g_postGwTH); cudaGetSymbolAddress((void**)&postGwTL, g_postGwTL);

    cudaFuncSetAttribute(mma_gemm_kernel<OP_GELU, true, false>,
                         cudaFuncAttributeMaxDynamicSharedMemorySize, GEMM_SMEM);
    cudaFuncSetAttribute(mma_gemm_kernel<OP_GATE, false, true>,
                         cudaFuncAttributeMaxDynamicSharedMemorySize, GEMM_SMEM);
    cudaFuncSetAttribute(mma_gemm_kernel<OP_NONE, true, true>,
                         cudaFuncAttributeMaxDynamicSharedMemorySize, GEMM_SMEM);
    cudaFuncSetAttribute(mma_gemm_kernel<OP_GATE, true, false>,
                         cudaFuncAttributeMaxDynamicSharedMemorySize, GEMM_SMEM);

    // --- operator prep (independent of x) ---
    build_a01_kernel<<<131072 / 256, 256>>>(core0, core1, a01);
    build_wttT_kernel<<<(DIN * DOUT) / 256, 256>>>(a01, core2, wttTH, wttTL);
    transpose_split_kernel<<<dim3(DIN / 32, DIN / 32), 256>>>(preDw, preDwTH, preDwTL, DIN, DIN);
    transpose_split_kernel<<<dim3(DIN / 32, DIN / 32), 256>>>(preGw, preGwTH, preGwTL, DIN, DIN);
    transpose_split_kernel<<<dim3(DOUT / 32, DOUT / 32), 256>>>(postDw, postDwTH, postDwTL, DOUT, DOUT);
    transpose_split_kernel<<<dim3(DOUT / 32, DOUT / 32), 256>>>(postGw, postGwTH, postGwTL, DOUT, DOUT);

    // --- pre block ---
    layernorm_split_kernel<DIN / 256, true><<<NTOK, 256>>>(
        x, preG, preB, ln1H, ln1L, xH, xL, DIN);
    mma_gemm_kernel<OP_GELU, true, false><<<dim3(NTOK / BM, DIN / BN), 256, GEMM_SMEM>>>(
        ln1H, ln1L, preDwTH, preDwTL, preDb, nullptr, nullptr,
        h1, nullptr, nullptr, NTOK, DIN, DIN);
    mma_gemm_kernel<OP_GATE, false, true><<<dim3(NTOK / BM, DIN / BN), 256, GEMM_SMEM>>>(
        xH, xL, preGwTH, preGwTL, preGb, h1, x,
        nullptr, hpreH, hpreL, NTOK, DIN, DIN);

    // --- TT contraction ---
    mma_gemm_kernel<OP_NONE, true, true><<<dim3(NTOK / BM, DOUT / BN), 256, GEMM_SMEM>>>(
        hpreH, hpreL, wttTH, wttTL, nullptr, nullptr, nullptr,
        t, tH, tL, NTOK, DOUT, DIN);

    // --- post block ---
    layernorm_split_kernel<DOUT / 256, false><<<NTOK, 256>>>(
        t, postG, postB, ln2H, ln2L, nullptr, nullptr, DOUT);
    mma_gemm_kernel<OP_GELU, true, false><<<dim3(NTOK / BM, DOUT / BN), 256, GEMM_SMEM>>>(
        ln2H, ln2L, postDwTH, postDwTL, postDb, nullptr, nullptr,
        h2, nullptr, nullptr, NTOK, DOUT, DOUT);
    mma_gemm_kernel<OP_GATE, true, false><<<dim3(NTOK / BM, DOUT / BN), 256, GEMM_SMEM>>>(
        tH, tL, postGwTH, postGwTL, postGb, h2, t,
        out, nullptr, nullptr, NTOK, DOUT, DOUT);
}

// round 9
// speedup vs baseline: 1.1494x; 1.1494x over previous
#include <cuda_runtime.h>
#include <cuda_bf16.h>
#include <math.h>
#include <stdint.h>

// ---------------------------------------------------------------------------
// HybridTTLayer via mma.sync bf16 tensor cores (plain sm_100 target — no
// tcgen05 available). fp32 emulated as bf16 hi+lo split, 3-product MMA.
//   LN -> dense(gelu)/gate -> TT(1024->4096, dense W_tt) -> LN -> dense/gate
// R9: CTA tile 128x128, warp tile 64x32, BK=32, 2-stage cp.async pipeline,
//     2 CTAs/SM co-residency to hide sync/epilogue bubbles.
// ---------------------------------------------------------------------------

#define NTOK   4096
#define DIN    1024
#define DOUT   4096

#define OP_NONE 0
#define OP_GELU 1
#define OP_GATE 2

// GEMM tiling
#define BM 128
#define BN 128
#define BK 32
#define STAGES 2
#define ROWB 80                        // smem bytes per 32-bf16 row (padded)
#define OFF_AH 0
#define OFF_AL 10240                   // 128*80
#define OFF_BH 20480
#define OFF_BL 30720
#define STAGE_BYTES 40960
#define GEMM_SMEM (STAGES * STAGE_BYTES)   // 81920 -> 2 CTAs/SM

// ------------------------- scratch (static device memory) ------------------
__device__ float g_h1 [NTOK * DIN];
__device__ float g_t  [NTOK * DOUT];
__device__ float g_h2 [NTOK * DOUT];
__device__ float g_a01[8 * 8 * 8 * 16 * 16];
__device__ __nv_bfloat16 g_xH   [NTOK * DIN],  g_xL   [NTOK * DIN];
__device__ __nv_bfloat16 g_ln1H [NTOK * DIN],  g_ln1L [NTOK * DIN];
__device__ __nv_bfloat16 g_hpreH[NTOK * DIN],  g_hpreL[NTOK * DIN];
__device__ __nv_bfloat16 g_tH   [NTOK * DOUT], g_tL   [NTOK * DOUT];
__device__ __nv_bfloat16 g_ln2H [NTOK * DOUT], g_ln2L [NTOK * DOUT];
__device__ __nv_bfloat16 g_preDwTH [DIN * DIN],   g_preDwTL [DIN * DIN];
__device__ __nv_bfloat16 g_preGwTH [DIN * DIN],   g_preGwTL [DIN * DIN];
__device__ __nv_bfloat16 g_wttTH   [DOUT * DIN],  g_wttTL   [DOUT * DIN];
__device__ __nv_bfloat16 g_postDwTH[DOUT * DOUT], g_postDwTL[DOUT * DOUT];
__device__ __nv_bfloat16 g_postGwTH[DOUT * DOUT], g_postGwTL[DOUT * DOUT];

// ------------------------- helpers -----------------------------------------
__device__ __forceinline__ uint32_t smem_u32(const void* p) {
    uint32_t a;
    asm("{ .reg .u64 t; cvta.to.shared.u64 t, %1; cvt.u32.u64 %0, t; }"
        : "=r"(a) : "l"(p));
    return a;
}
__device__ __forceinline__ void cp16(uint32_t s, const void* g) {
    asm volatile("cp.async.cg.shared.global [%0], [%1], 16;" :: "r"(s), "l"(g));
}
#define CP_COMMIT() asm volatile("cp.async.commit_group;")
#define CP_WAIT1()  asm volatile("cp.async.wait_group 1;")
#define CP_WAIT0()  asm volatile("cp.async.wait_group 0;")

__device__ __forceinline__ void ldmx4(uint32_t* r, uint32_t a) {
    asm volatile("ldmatrix.sync.aligned.m8n8.x4.shared.b16 {%0,%1,%2,%3}, [%4];"
        : "=r"(r[0]), "=r"(r[1]), "=r"(r[2]), "=r"(r[3]) : "r"(a));
}
__device__ __forceinline__ void mma_bf16(float* d, const uint32_t* a, const uint32_t* b) {
    asm volatile("mma.sync.aligned.m16n8k16.row.col.f32.bf16.bf16.f32 "
        "{%0,%1,%2,%3}, {%4,%5,%6,%7}, {%8,%9}, {%0,%1,%2,%3};"
        : "+f"(d[0]), "+f"(d[1]), "+f"(d[2]), "+f"(d[3])
        : "r"(a[0]), "r"(a[1]), "r"(a[2]), "r"(a[3]), "r"(b[0]), "r"(b[1]));
}
__device__ __forceinline__ float gelu_exact(float v) {
    return 0.5f * v * (1.0f + erff(v * 0.70710678118654752f));
}
__device__ __forceinline__ float sigmoidf_(float v) {
    return 1.0f / (1.0f + __expf(-v));
}
__device__ __forceinline__ void split_bf16(float v, __nv_bfloat16& h, __nv_bfloat16& l) {
    h = __float2bfloat16_rn(v);
    l = __float2bfloat16_rn(v - __bfloat162float(h));
}

// ------------------------- layernorm (emits bf16 hi/lo) ----------------------
template <int EPT, bool SPLIT_IN>
__global__ __launch_bounds__(256) void layernorm_split_kernel(
    const float* __restrict__ in, const float* __restrict__ gamma,
    const float* __restrict__ beta,
    __nv_bfloat16* __restrict__ oH, __nv_bfloat16* __restrict__ oL,
    __nv_bfloat16* __restrict__ iH, __nv_bfloat16* __restrict__ iL, int D)
{
    const int row = blockIdx.x;
    const int tid = threadIdx.x;
    const float* rp = in + (size_t)row * D;

    float v[EPT];
    float s = 0.f;
#pragma unroll
    for (int e = 0; e < EPT; e++) { v[e] = rp[tid + e * 256]; s += v[e]; }

    __shared__ float red[8];
    __shared__ float sMean, sVar;
#pragma unroll
    for (int o = 16; o > 0; o >>= 1) s += __shfl_down_sync(0xffffffffu, s, o);
    if ((tid & 31) == 0) red[tid >> 5] = s;
    __syncthreads();
    if (tid < 8) {
        float w = red[tid];
#pragma unroll
        for (int o = 4; o > 0; o >>= 1) w += __shfl_down_sync(0xffu, w, o);
        if (tid == 0) sMean = w / (float)D;
    }
    __syncthreads();
    const float mean = sMean;

    float q = 0.f;
#pragma unroll
    for (int e = 0; e < EPT; e++) { float d = v[e] - mean; q += d * d; }
#pragma unroll
    for (int o = 16; o > 0; o >>= 1) q += __shfl_down_sync(0xffffffffu, q, o);
    if ((tid & 31) == 0) red[tid >> 5] = q;
    __syncthreads();
    if (tid < 8) {
        float w = red[tid];
#pragma unroll
        for (int o = 4; o > 0; o >>= 1) w += __shfl_down_sync(0xffu, w, o);
        if (tid == 0) sVar = w / (float)D;
    }
    __syncthreads();
    const float inv = rsqrtf(sVar + 1e-6f);

    const size_t rb = (size_t)row * D;
#pragma unroll
    for (int e = 0; e < EPT; e++) {
        int c = tid + e * 256;
        float o = (v[e] - mean) * inv * gamma[c] + beta[c];
        __nv_bfloat16 h, l;
        split_bf16(o, h, l);
        oH[rb + c] = h; oL[rb + c] = l;
        if (SPLIT_IN) {
            split_bf16(v[e], h, l);
            iH[rb + c] = h; iL[rb + c] = l;
        }
    }
}

// ------------------------- TT operator materialization ----------------------
__global__ __launch_bounds__(256) void build_a01_kernel(
    const float* __restrict__ c0, const float* __restrict__ c1,
    float* __restrict__ a01)
{
    int idx = blockIdx.x * 256 + threadIdx.x;   // 131072
    int s = idx & 15, y = (idx >> 4) & 15, b = (idx >> 8) & 7;
    int x = (idx >> 11) & 7, a = idx >> 14;
    float acc = 0.f;
#pragma unroll
    for (int r = 0; r < 16; r++)
        acc += c0[a * 128 + x * 16 + r] * c1[((r * 8 + b) * 16 + y) * 16 + s];
    a01[idx] = acc;
}

// wttT[out][in] as bf16 hi/lo; out = x*512+y*32+z; in = a*128+b*16+c
__global__ __launch_bounds__(256) void build_wttT_kernel(
    const float* __restrict__ a01, const float* __restrict__ c2,
    __nv_bfloat16* __restrict__ wH, __nv_bfloat16* __restrict__ wL)
{
    int idx = blockIdx.x * 256 + threadIdx.x;   // 4096*1024
    int in  = idx & 1023;
    int out = idx >> 10;
    int z = out & 31, y = (out >> 5) & 15, x = out >> 9;
    int c = in & 15,  b = (in >> 4) & 7,   a = in >> 7;
    const float* ap = a01 + (((a * 8 + x) * 8 + b) * 16 + y) * 16;
    float acc = 0.f;
#pragma unroll
    for (int s = 0; s < 16; s++)
        acc += ap[s] * c2[(s * 16 + c) * 32 + z];
    __nv_bfloat16 h, l;
    split_bf16(acc, h, l);
    wH[idx] = h; wL[idx] = l;
}

// ------------------------- weight transpose + split --------------------------
__global__ __launch_bounds__(256) void transpose_split_kernel(
    const float* __restrict__ in, __nv_bfloat16* __restrict__ oH,
    __nv_bfloat16* __restrict__ oL, int K, int N)
{
    __shared__ float tile[32][33];
    int n0 = blockIdx.x * 32, k0 = blockIdx.y * 32;
    int tx = threadIdx.x & 31, ty = threadIdx.x >> 5;
#pragma unroll
    for (int i = 0; i < 4; i++)
        tile[ty + i * 8][tx] = in[(size_t)(k0 + ty + i * 8) * N + n0 + tx];
    __syncthreads();
#pragma unroll
    for (int i = 0; i < 4; i++) {
        float v = tile[tx][ty + i * 8];
        __nv_bfloat16 h, l;
        split_bf16(v, h, l);
        size_t o = (size_t)(n0 + ty + i * 8) * K + k0 + tx;
        oH[o] = h; oL[o] = l;
    }
}

// ------------------------- mma.sync GEMM ------------------------------------
// C = A[M,K] @ Bt[N,K]^T with bf16 hi/lo 3-product emulation.
__device__ __forceinline__ void load_stage(
    uint32_t sbase,
    const __nv_bfloat16* __restrict__ Ah, const __nv_bfloat16* __restrict__ Al,
    const __nv_bfloat16* __restrict__ Bh, const __nv_bfloat16* __restrict__ Bl,
    int aRow0, int bRow0, int K, int k0, int tid)
{
    // A and B: 128 rows x 4 16B-cols = 512 ops / 256 threads = 2 each
#pragma unroll
    for (int i = 0; i < 2; i++) {
        int idx = tid + i * 256;
        int r = idx >> 2, c = idx & 3;
        uint32_t so = (uint32_t)(r * ROWB + c * 16);
        size_t ga = (size_t)(aRow0 + r) * K + k0 + c * 8;
        size_t gb = (size_t)(bRow0 + r) * K + k0 + c * 8;
        cp16(sbase + OFF_AH + so, Ah + ga);
        cp16(sbase + OFF_AL + so, Al + ga);
        cp16(sbase + OFF_BH + so, Bh + gb);
        cp16(sbase + OFF_BL + so, Bl + gb);
    }
}

template <int OP>
__device__ __forceinline__ float epi_op(float acc, float b, float h, float r) {
    if (OP == OP_GELU) return gelu_exact(acc + b);
    if (OP == OP_GATE) { float g = sigmoidf_(acc + b); return g * h + (1.f - g) * r; }
    return acc;
}

template <int OP, bool WF32, bool WSPLIT>
__global__ __launch_bounds__(256, 2) void mma_gemm_kernel(
    const __nv_bfloat16* __restrict__ Ah, const __nv_bfloat16* __restrict__ Al,
    const __nv_bfloat16* __restrict__ Bh, const __nv_bfloat16* __restrict__ Bl,
    const float* __restrict__ bias, const float* __restrict__ Hm,
    const float* __restrict__ Rm,
    float* __restrict__ CF, __nv_bfloat16* __restrict__ CH,
    __nv_bfloat16* __restrict__ CL, int M, int N, int K)
{
    extern __shared__ char smem[];
    const uint32_t sm = smem_u32(smem);
    const int tid  = threadIdx.x;
    const int lane = tid & 31;
    const int wid  = tid >> 5;
    const int blockM = blockIdx.x * BM;   // x fastest over M: B slab reused in L2
    const int blockN = blockIdx.y * BN;
    const int wm = (wid >> 2) * 64;       // 2 warp rows
    const int wn = (wid & 3) * 32;        // 4 warp cols
    const int nk = K / BK;

    float acc[4][4][4];
#pragma unroll
    for (int i = 0; i < 4; i++)
#pragma unroll
        for (int j = 0; j < 4; j++)
#pragma unroll
            for (int e = 0; e < 4; e++) acc[i][j][e] = 0.f;

    // prologue: stage 0
    load_stage(sm, Ah, Al, Bh, Bl, blockM, blockN, K, 0, tid);
    CP_COMMIT();

    const uint32_t aRowOff = (uint32_t)((lane & 15) * ROWB);
    const uint32_t aColOff = (uint32_t)((lane >> 4) * 16);
    const uint32_t bRowOff = (uint32_t)((wn + (lane & 7) + ((lane >> 4) << 3)) * ROWB);
    const uint32_t bColOff = (uint32_t)(((lane >> 3) & 1) * 16);

    for (int t = 0; t < nk; t++) {
        // ensure buffer (t+1)%2 is no longer being read (compute t-1 done)
        if (t > 0) __syncthreads();
        const bool more = (t + 1 < nk);
        if (more) {
            load_stage(sm + ((t + 1) & 1) * STAGE_BYTES, Ah, Al, Bh, Bl,
                       blockM, blockN, K, (t + 1) * BK, tid);
            CP_COMMIT();
            CP_WAIT1();
        } else {
            CP_WAIT0();
        }
        __syncthreads();

        const uint32_t sb = sm + (t & 1) * STAGE_BYTES;
#pragma unroll
        for (int ks = 0; ks < 2; ks++) {
            uint32_t ah[4][4], al[4][4];
            const uint32_t abase = sb + ks * 32 + aColOff + aRowOff;
#pragma unroll
            for (int mt = 0; mt < 4; mt++) {
                ldmx4(ah[mt], abase + OFF_AH + (uint32_t)((wm + mt * 16) * ROWB));
                ldmx4(al[mt], abase + OFF_AL + (uint32_t)((wm + mt * 16) * ROWB));
            }
            const uint32_t bbase = sb + ks * 32 + bColOff + bRowOff;
#pragma unroll
            for (int g = 0; g < 2; g++) {
                uint32_t bh0[4], bl0[4];
                const uint32_t bg = bbase + (uint32_t)(g * 16 * ROWB);
                ldmx4(bh0, bg + OFF_BH);
                ldmx4(bl0, bg + OFF_BL);
#pragma unroll
                for (int mt = 0; mt < 4; mt++) {
                    mma_bf16(acc[mt][2 * g],     ah[mt], bh0 + 0);
                    mma_bf16(acc[mt][2 * g],     ah[mt], bl0 + 0);
                    mma_bf16(acc[mt][2 * g],     al[mt], bh0 + 0);
                    mma_bf16(acc[mt][2 * g + 1], ah[mt], bh0 + 2);
                    mma_bf16(acc[mt][2 * g + 1], ah[mt], bl0 + 2);
                    mma_bf16(acc[mt][2 * g + 1], al[mt], bh0 + 2);
                }
            }
        }
    }

    // ---------------- epilogue ----------------
    const int r0 = lane >> 2;
    const int c0 = (lane & 3) * 2;
#pragma unroll
    for (int mt = 0; mt < 4; mt++) {
#pragma unroll
        for (int half = 0; half < 2; half++) {
            const int m = blockM + wm + mt * 16 + r0 + half * 8;
            const size_t base = (size_t)m * N;
#pragma unroll
            for (int nt = 0; nt < 4; nt++) {
                const int n = blockN + wn + nt * 8 + c0;
                float v0 = acc[mt][nt][half * 2 + 0];
                float v1 = acc[mt][nt][half * 2 + 1];
                float b0 = 0.f, b1 = 0.f, h0 = 0.f, h1 = 0.f, rr0 = 0.f, rr1 = 0.f;
                if (OP != OP_NONE) { b0 = bias[n]; b1 = bias[n + 1]; }
                if (OP == OP_GATE) {
                    float2 hh = *(const float2*)(Hm + base + n);
                    float2 rr = *(const float2*)(Rm + base + n);
                    h0 = hh.x; h1 = hh.y; rr0 = rr.x; rr1 = rr.y;
                }
                v0 = epi_op<OP>(v0, b0, h0, rr0);
                v1 = epi_op<OP>(v1, b1, h1, rr1);
                if (WF32) *(float2*)(CF + base + n) = make_float2(v0, v1);
                if (WSPLIT) {
                    __nv_bfloat16 hA, lA, hB, lB;
                    split_bf16(v0, hA, lA);
                    split_bf16(v1, hB, lB);
                    __nv_bfloat162 ph; ph.x = hA; ph.y = hB;
                    __nv_bfloat162 pl; pl.x = lA; pl.y = lB;
                    *(__nv_bfloat162*)(CH + base + n) = ph;
                    *(__nv_bfloat162*)(CL + base + n) = pl;
                }
            }
        }
    }
}

// ------------------------- launch ------------------------------------------
extern "C" void kernel_launch(void* const* d_in, const int* in_sizes, int n_in,
                              void* d_out, int out_size)
{
    const float* x      = (const float*)d_in[0];
    const float* preG   = (const float*)d_in[1];
    const float* preB   = (const float*)d_in[2];
    const float* preDw  = (const float*)d_in[3];
    const float* preDb  = (const float*)d_in[4];
    const float* preGw  = (const float*)d_in[5];
    const float* preGb  = (const float*)d_in[6];
    const float* core0  = (const float*)d_in[7];
    const float* core1  = (const float*)d_in[8];
    const float* core2  = (const float*)d_in[9];
    const float* postG  = (const float*)d_in[10];
    const float* postB  = (const float*)d_in[11];
    const float* postDw = (const float*)d_in[12];
    const float* postDb = (const float*)d_in[13];
    const float* postGw = (const float*)d_in[14];
    const float* postGb = (const float*)d_in[15];
    float* out = (float*)d_out;

    float *h1, *t, *h2, *a01;
    cudaGetSymbolAddress((void**)&h1,  g_h1);
    cudaGetSymbolAddress((void**)&t,   g_t);
    cudaGetSymbolAddress((void**)&h2,  g_h2);
    cudaGetSymbolAddress((void**)&a01, g_a01);

    __nv_bfloat16 *xH, *xL, *ln1H, *ln1L, *hpreH, *hpreL, *tH, *tL, *ln2H, *ln2L;
    __nv_bfloat16 *preDwTH, *preDwTL, *preGwTH, *preGwTL;
    __nv_bfloat16 *wttTH, *wttTL, *postDwTH, *postDwTL, *postGwTH, *postGwTL;
    cudaGetSymbolAddress((void**)&xH,    g_xH);    cudaGetSymbolAddress((void**)&xL,    g_xL);
    cudaGetSymbolAddress((void**)&ln1H,  g_ln1H);  cudaGetSymbolAddress((void**)&ln1L,  g_ln1L);
    cudaGetSymbolAddress((void**)&hpreH, g_hpreH); cudaGetSymbolAddress((void**)&hpreL, g_hpreL);
    cudaGetSymbolAddress((void**)&tH,    g_tH);    cudaGetSymbolAddress((void**)&tL,    g_tL);
    cudaGetSymbolAddress((void**)&ln2H,  g_ln2H);  cudaGetSymbolAddress((void**)&ln2L,  g_ln2L);
    cudaGetSymbolAddress((void**)&preDwTH,  g_preDwTH);  cudaGetSymbolAddress((void**)&preDwTL,  g_preDwTL);
    cudaGetSymbolAddress((void**)&preGwTH,  g_preGwTH);  cudaGetSymbolAddress((void**)&preGwTL,  g_preGwTL);
    cudaGetSymbolAddress((void**)&wttTH,    g_wttTH);    cudaGetSymbolAddress((void**)&wttTL,    g_wttTL);
    cudaGetSymbolAddress((void**)&postDwTH, g_postDwTH); cudaGetSymbolAddress((void**)&postDwTL, g_postDwTL);
    cudaGetSymbolAddress((void**)&postGwTH, g_postGwTH); cudaGetSymbolAddress((void**)&postGwTL, g_postGwTL);

    cudaFuncSetAttribute(mma_gemm_kernel<OP_GELU, true, false>,
                         cudaFuncAttributeMaxDynamicSharedMemorySize, GEMM_SMEM);
    cudaFuncSetAttribute(mma_gemm_kernel<OP_GATE, false, true>,
                         cudaFuncAttributeMaxDynamicSharedMemorySize, GEMM_SMEM);
    cudaFuncSetAttribute(mma_gemm_kernel<OP_NONE, true, true>,
                         cudaFuncAttributeMaxDynamicSharedMemorySize, GEMM_SMEM);
    cudaFuncSetAttribute(mma_gemm_kernel<OP_GATE, true, false>,
                         cudaFuncAttributeMaxDynamicSharedMemorySize, GEMM_SMEM);

    // --- operator prep (independent of x) ---
    build_a01_kernel<<<131072 / 256, 256>>>(core0, core1, a01);
    build_wttT_kernel<<<(DIN * DOUT) / 256, 256>>>(a01, core2, wttTH, wttTL);
    transpose_split_kernel<<<dim3(DIN / 32, DIN / 32), 256>>>(preDw, preDwTH, preDwTL, DIN, DIN);
    transpose_split_kernel<<<dim3(DIN / 32, DIN / 32), 256>>>(preGw, preGwTH, preGwTL, DIN, DIN);
    transpose_split_kernel<<<dim3(DOUT / 32, DOUT / 32), 256>>>(postDw, postDwTH, postDwTL, DOUT, DOUT);
    transpose_split_kernel<<<dim3(DOUT / 32, DOUT / 32), 256>>>(postGw, postGwTH, postGwTL, DOUT, DOUT);

    // --- pre block ---
    layernorm_split_kernel<DIN / 256, true><<<NTOK, 256>>>(
        x, preG, preB, ln1H, ln1L, xH, xL, DIN);
    mma_gemm_kernel<OP_GELU, true, false><<<dim3(NTOK / BM, DIN / BN), 256, GEMM_SMEM>>>(
        ln1H, ln1L, preDwTH, preDwTL, preDb, nullptr, nullptr,
        h1, nullptr, nullptr, NTOK, DIN, DIN);
    mma_gemm_kernel<OP_GATE, false, true><<<dim3(NTOK / BM, DIN / BN), 256, GEMM_SMEM>>>(
        xH, xL, preGwTH, preGwTL, preGb, h1, x,
        nullptr, hpreH, hpreL, NTOK, DIN, DIN);

    // --- TT contraction ---
    mma_gemm_kernel<OP_NONE, true, true><<<dim3(NTOK / BM, DOUT / BN), 256, GEMM_SMEM>>>(
        hpreH, hpreL, wttTH, wttTL, nullptr, nullptr, nullptr,
        t, tH, tL, NTOK, DOUT, DIN);

    // --- post block ---
    layernorm_split_kernel<DOUT / 256, false><<<NTOK, 256>>>(
        t, postG, postB, ln2H, ln2L, nullptr, nullptr, DOUT);
    mma_gemm_kernel<OP_GELU, true, false><<<dim3(NTOK / BM, DOUT / BN), 256, GEMM_SMEM>>>(
        ln2H, ln2L, postDwTH, postDwTL, postDb, nullptr, nullptr,
        h2, nullptr, nullptr, NTOK, DOUT, DOUT);
    mma_gemm_kernel<OP_GATE, true, false><<<dim3(NTOK / BM, DOUT / BN), 256, GEMM_SMEM>>>(
        tH, tL, postGwTH, postGwTL, postGb, h2, t,
        out, nullptr, nullptr, NTOK, DOUT, DOUT);
}

// round 10
// speedup vs baseline: 1.3281x; 1.1555x over previous
#include <cuda_runtime.h>
#include <cuda_bf16.h>
#include <math.h>
#include <stdint.h>

// ---------------------------------------------------------------------------
// HybridTTLayer via mma.sync bf16 tensor cores (plain sm_100 target — no
// tcgen05 available). fp32 emulated as bf16 hi+lo split, 3-product MMA.
//   LN -> dense(gelu)/gate -> TT(1024->4096, dense W_tt) -> LN -> dense/gate
// R10: CTA 128x128, warp 64x32, BK=32, 3-stage pipeline w/ XOR-swizzled 64B
//      rows (32KB/stage -> 96KB, 2 CTAs/SM), product-major MMA ordering.
// ---------------------------------------------------------------------------

#define NTOK   4096
#define DIN    1024
#define DOUT   4096

#define OP_NONE 0
#define OP_GELU 1
#define OP_GATE 2

// GEMM tiling
#define BM 128
#define BN 128
#define BK 32
#define STAGES 3
#define ROWB 64                        // smem bytes per 32-bf16 row (no pad)
#define OFF_AH 0
#define OFF_AL 8192                    // 128*64
#define OFF_BH 16384
#define OFF_BL 24576
#define STAGE_BYTES 32768
#define GEMM_SMEM (STAGES * STAGE_BYTES)   // 98304 -> 2 CTAs/SM

// swizzled byte offset of 16B chunk c (0..3) in row r
__device__ __forceinline__ uint32_t swz(int r, int c) {
    return (uint32_t)(r * 64 + ((c ^ ((r >> 1) & 3)) << 4));
}

// ------------------------- scratch (static device memory) ------------------
__device__ float g_h1 [NTOK * DIN];
__device__ float g_t  [NTOK * DOUT];
__device__ float g_h2 [NTOK * DOUT];
__device__ float g_a01[8 * 8 * 8 * 16 * 16];
__device__ __nv_bfloat16 g_xH   [NTOK * DIN],  g_xL   [NTOK * DIN];
__device__ __nv_bfloat16 g_ln1H [NTOK * DIN],  g_ln1L [NTOK * DIN];
__device__ __nv_bfloat16 g_hpreH[NTOK * DIN],  g_hpreL[NTOK * DIN];
__device__ __nv_bfloat16 g_tH   [NTOK * DOUT], g_tL   [NTOK * DOUT];
__device__ __nv_bfloat16 g_ln2H [NTOK * DOUT], g_ln2L [NTOK * DOUT];
__device__ __nv_bfloat16 g_preDwTH [DIN * DIN],   g_preDwTL [DIN * DIN];
__device__ __nv_bfloat16 g_preGwTH [DIN * DIN],   g_preGwTL [DIN * DIN];
__device__ __nv_bfloat16 g_wttTH   [DOUT * DIN],  g_wttTL   [DOUT * DIN];
__device__ __nv_bfloat16 g_postDwTH[DOUT * DOUT], g_postDwTL[DOUT * DOUT];
__device__ __nv_bfloat16 g_postGwTH[DOUT * DOUT], g_postGwTL[DOUT * DOUT];

// ------------------------- helpers -----------------------------------------
__device__ __forceinline__ uint32_t smem_u32(const void* p) {
    uint32_t a;
    asm("{ .reg .u64 t; cvta.to.shared.u64 t, %1; cvt.u32.u64 %0, t; }"
        : "=r"(a) : "l"(p));
    return a;
}
__device__ __forceinline__ void cp16(uint32_t s, const void* g) {
    asm volatile("cp.async.cg.shared.global [%0], [%1], 16;" :: "r"(s), "l"(g));
}
#define CP_COMMIT() asm volatile("cp.async.commit_group;")
#define CP_WAIT1()  asm volatile("cp.async.wait_group 1;")
#define CP_WAIT0()  asm volatile("cp.async.wait_group 0;")

__device__ __forceinline__ void ldmx4(uint32_t* r, uint32_t a) {
    asm volatile("ldmatrix.sync.aligned.m8n8.x4.shared.b16 {%0,%1,%2,%3}, [%4];"
        : "=r"(r[0]), "=r"(r[1]), "=r"(r[2]), "=r"(r[3]) : "r"(a));
}
__device__ __forceinline__ void mma_bf16(float* d, const uint32_t* a, const uint32_t* b) {
    asm volatile("mma.sync.aligned.m16n8k16.row.col.f32.bf16.bf16.f32 "
        "{%0,%1,%2,%3}, {%4,%5,%6,%7}, {%8,%9}, {%0,%1,%2,%3};"
        : "+f"(d[0]), "+f"(d[1]), "+f"(d[2]), "+f"(d[3])
        : "r"(a[0]), "r"(a[1]), "r"(a[2]), "r"(a[3]), "r"(b[0]), "r"(b[1]));
}
__device__ __forceinline__ float gelu_exact(float v) {
    return 0.5f * v * (1.0f + erff(v * 0.70710678118654752f));
}
__device__ __forceinline__ float sigmoidf_(float v) {
    return 1.0f / (1.0f + __expf(-v));
}
__device__ __forceinline__ void split_bf16(float v, __nv_bfloat16& h, __nv_bfloat16& l) {
    h = __float2bfloat16_rn(v);
    l = __float2bfloat16_rn(v - __bfloat162float(h));
}

// ------------------------- layernorm (emits bf16 hi/lo) ----------------------
template <int EPT, bool SPLIT_IN>
__global__ __launch_bounds__(256) void layernorm_split_kernel(
    const float* __restrict__ in, const float* __restrict__ gamma,
    const float* __restrict__ beta,
    __nv_bfloat16* __restrict__ oH, __nv_bfloat16* __restrict__ oL,
    __nv_bfloat16* __restrict__ iH, __nv_bfloat16* __restrict__ iL, int D)
{
    const int row = blockIdx.x;
    const int tid = threadIdx.x;
    const float* rp = in + (size_t)row * D;

    float v[EPT];
    float s = 0.f;
#pragma unroll
    for (int e = 0; e < EPT; e++) { v[e] = rp[tid + e * 256]; s += v[e]; }

    __shared__ float red[8];
    __shared__ float sMean, sVar;
#pragma unroll
    for (int o = 16; o > 0; o >>= 1) s += __shfl_down_sync(0xffffffffu, s, o);
    if ((tid & 31) == 0) red[tid >> 5] = s;
    __syncthreads();
    if (tid < 8) {
        float w = red[tid];
#pragma unroll
        for (int o = 4; o > 0; o >>= 1) w += __shfl_down_sync(0xffu, w, o);
        if (tid == 0) sMean = w / (float)D;
    }
    __syncthreads();
    const float mean = sMean;

    float q = 0.f;
#pragma unroll
    for (int e = 0; e < EPT; e++) { float d = v[e] - mean; q += d * d; }
#pragma unroll
    for (int o = 16; o > 0; o >>= 1) q += __shfl_down_sync(0xffffffffu, q, o);
    if ((tid & 31) == 0) red[tid >> 5] = q;
    __syncthreads();
    if (tid < 8) {
        float w = red[tid];
#pragma unroll
        for (int o = 4; o > 0; o >>= 1) w += __shfl_down_sync(0xffu, w, o);
        if (tid == 0) sVar = w / (float)D;
    }
    __syncthreads();
    const float inv = rsqrtf(sVar + 1e-6f);

    const size_t rb = (size_t)row * D;
#pragma unroll
    for (int e = 0; e < EPT; e++) {
        int c = tid + e * 256;
        float o = (v[e] - mean) * inv * gamma[c] + beta[c];
        __nv_bfloat16 h, l;
        split_bf16(o, h, l);
        oH[rb + c] = h; oL[rb + c] = l;
        if (SPLIT_IN) {
            split_bf16(v[e], h, l);
            iH[rb + c] = h; iL[rb + c] = l;
        }
    }
}

// ------------------------- TT operator materialization ----------------------
__global__ __launch_bounds__(256) void build_a01_kernel(
    const float* __restrict__ c0, const float* __restrict__ c1,
    float* __restrict__ a01)
{
    int idx = blockIdx.x * 256 + threadIdx.x;   // 131072
    int s = idx & 15, y = (idx >> 4) & 15, b = (idx >> 8) & 7;
    int x = (idx >> 11) & 7, a = idx >> 14;
    float acc = 0.f;
#pragma unroll
    for (int r = 0; r < 16; r++)
        acc += c0[a * 128 + x * 16 + r] * c1[((r * 8 + b) * 16 + y) * 16 + s];
    a01[idx] = acc;
}

// wttT[out][in] as bf16 hi/lo; out = x*512+y*32+z; in = a*128+b*16+c
__global__ __launch_bounds__(256) void build_wttT_kernel(
    const float* __restrict__ a01, const float* __restrict__ c2,
    __nv_bfloat16* __restrict__ wH, __nv_bfloat16* __restrict__ wL)
{
    int idx = blockIdx.x * 256 + threadIdx.x;   // 4096*1024
    int in  = idx & 1023;
    int out = idx >> 10;
    int z = out & 31, y = (out >> 5) & 15, x = out >> 9;
    int c = in & 15,  b = (in >> 4) & 7,   a = in >> 7;
    const float* ap = a01 + (((a * 8 + x) * 8 + b) * 16 + y) * 16;
    float acc = 0.f;
#pragma unroll
    for (int s = 0; s < 16; s++)
        acc += ap[s] * c2[(s * 16 + c) * 32 + z];
    __nv_bfloat16 h, l;
    split_bf16(acc, h, l);
    wH[idx] = h; wL[idx] = l;
}

// ------------------------- weight transpose + split --------------------------
__global__ __launch_bounds__(256) void transpose_split_kernel(
    const float* __restrict__ in, __nv_bfloat16* __restrict__ oH,
    __nv_bfloat16* __restrict__ oL, int K, int N)
{
    __shared__ float tile[32][33];
    int n0 = blockIdx.x * 32, k0 = blockIdx.y * 32;
    int tx = threadIdx.x & 31, ty = threadIdx.x >> 5;
#pragma unroll
    for (int i = 0; i < 4; i++)
        tile[ty + i * 8][tx] = in[(size_t)(k0 + ty + i * 8) * N + n0 + tx];
    __syncthreads();
#pragma unroll
    for (int i = 0; i < 4; i++) {
        float v = tile[tx][ty + i * 8];
        __nv_bfloat16 h, l;
        split_bf16(v, h, l);
        size_t o = (size_t)(n0 + ty + i * 8) * K + k0 + tx;
        oH[o] = h; oL[o] = l;
    }
}

// ------------------------- mma.sync GEMM ------------------------------------
// C = A[M,K] @ Bt[N,K]^T with bf16 hi/lo 3-product emulation.
__device__ __forceinline__ void load_stage(
    uint32_t sbase,
    const __nv_bfloat16* __restrict__ Ah, const __nv_bfloat16* __restrict__ Al,
    const __nv_bfloat16* __restrict__ Bh, const __nv_bfloat16* __restrict__ Bl,
    int aRow0, int bRow0, int K, int k0, int tid)
{
    // A and B: 128 rows x 4 16B-chunks = 512 ops / 256 threads = 2 each
#pragma unroll
    for (int i = 0; i < 2; i++) {
        int idx = tid + i * 256;
        int r = idx >> 2, c = idx & 3;
        uint32_t so = swz(r, c);
        size_t ga = (size_t)(aRow0 + r) * K + k0 + c * 8;
        size_t gb = (size_t)(bRow0 + r) * K + k0 + c * 8;
        cp16(sbase + OFF_AH + so, Ah + ga);
        cp16(sbase + OFF_AL + so, Al + ga);
        cp16(sbase + OFF_BH + so, Bh + gb);
        cp16(sbase + OFF_BL + so, Bl + gb);
    }
}

template <int OP>
__device__ __forceinline__ float epi_op(float acc, float b, float h, float r) {
    if (OP == OP_GELU) return gelu_exact(acc + b);
    if (OP == OP_GATE) { float g = sigmoidf_(acc + b); return g * h + (1.f - g) * r; }
    return acc;
}

template <int OP, bool WF32, bool WSPLIT>
__global__ __launch_bounds__(256, 2) void mma_gemm_kernel(
    const __nv_bfloat16* __restrict__ Ah, const __nv_bfloat16* __restrict__ Al,
    const __nv_bfloat16* __restrict__ Bh, const __nv_bfloat16* __restrict__ Bl,
    const float* __restrict__ bias, const float* __restrict__ Hm,
    const float* __restrict__ Rm,
    float* __restrict__ CF, __nv_bfloat16* __restrict__ CH,
    __nv_bfloat16* __restrict__ CL, int M, int N, int K)
{
    extern __shared__ char smem[];
    const uint32_t sm = smem_u32(smem);
    const int tid  = threadIdx.x;
    const int lane = tid & 31;
    const int wid  = tid >> 5;
    const int blockM = blockIdx.x * BM;   // x fastest over M: B slab reused in L2
    const int blockN = blockIdx.y * BN;
    const int wm = (wid >> 2) * 64;       // 2 warp rows
    const int wn = (wid & 3) * 32;        // 4 warp cols
    const int nk = K / BK;

    float acc[4][4][4];
#pragma unroll
    for (int i = 0; i < 4; i++)
#pragma unroll
        for (int j = 0; j < 4; j++)
#pragma unroll
            for (int e = 0; e < 4; e++) acc[i][j][e] = 0.f;

    // prologue: stages 0,1
#pragma unroll
    for (int s = 0; s < STAGES - 1; s++) {
        load_stage(sm + s * STAGE_BYTES, Ah, Al, Bh, Bl, blockM, blockN, K, s * BK, tid);
        CP_COMMIT();
    }

    // per-lane fragment row/chunk pieces (swizzle factor is lane-invariant
    // across mt/ks because mt*16 and wm are multiples of 8)
    const int aRow = lane & 15;                 // + wm + mt*16
    const int aHi  = lane >> 4;                 // chunk parity within k16
    const int bRow = wn + (lane & 7) + ((lane >> 4) << 3);
    const int bHi  = (lane >> 3) & 1;
    const int sA = ((aRow >> 1) & 3);
    const int sB = ((bRow >> 1) & 3);

    for (int t = 0; t < nk; t++) {
        CP_WAIT1();
        __syncthreads();
        const int pf = t + STAGES - 1;
        if (pf < nk)
            load_stage(sm + (pf % STAGES) * STAGE_BYTES, Ah, Al, Bh, Bl,
                       blockM, blockN, K, pf * BK, tid);
        CP_COMMIT();

        const uint32_t sb = sm + (t % STAGES) * STAGE_BYTES;
#pragma unroll
        for (int ks = 0; ks < 2; ks++) {
            const uint32_t aChunk = (uint32_t)(((ks * 2 + aHi) ^ sA) << 4);
            const uint32_t bChunk = (uint32_t)(((ks * 2 + bHi) ^ sB) << 4);
            uint32_t ah[4][4], al[4][4];
#pragma unroll
            for (int mt = 0; mt < 4; mt++) {
                const uint32_t ra = (uint32_t)((wm + mt * 16 + aRow) * 64) + aChunk;
                ldmx4(ah[mt], sb + OFF_AH + ra);
                ldmx4(al[mt], sb + OFF_AL + ra);
            }
            const uint32_t rb = (uint32_t)(bRow * 64) + bChunk;
            uint32_t bh0[4], bl0[4];
            ldmx4(bh0, sb + OFF_BH + rb);
            ldmx4(bl0, sb + OFF_BL + rb);
            // product-major ordering: consecutive MMAs hit distinct accumulators
#pragma unroll
            for (int mt = 0; mt < 4; mt++) mma_bf16(acc[mt][0 + 0], ah[mt], bh0 + 0);
#pragma unroll
            for (int mt = 0; mt < 4; mt++) mma_bf16(acc[mt][0 + 1], ah[mt], bh0 + 2);
#pragma unroll
            for (int mt = 0; mt < 4; mt++) mma_bf16(acc[mt][0 + 0], ah[mt], bl0 + 0);
#pragma unroll
            for (int mt = 0; mt < 4; mt++) mma_bf16(acc[mt][0 + 1], ah[mt], bl0 + 2);
#pragma unroll
            for (int mt = 0; mt < 4; mt++) mma_bf16(acc[mt][0 + 0], al[mt], bh0 + 0);
#pragma unroll
            for (int mt = 0; mt < 4; mt++) mma_bf16(acc[mt][0 + 1], al[mt], bh0 + 2);
            // second 16-col group (g=1) via upper 16 rows of B tile fragment:
            // B fragment rows wn..wn+31 are covered by two ldmatrix tiles; load them
            uint32_t bh1[4], bl1[4];
            const uint32_t rb1 = (uint32_t)((bRow + 16) * 64) + bChunk;
            ldmx4(bh1, sb + OFF_BH + rb1);
            ldmx4(bl1, sb + OFF_BL + rb1);
#pragma unroll
            for (int mt = 0; mt < 4; mt++) mma_bf16(acc[mt][2 + 0], ah[mt], bh1 + 0);
#pragma unroll
            for (int mt = 0; mt < 4; mt++) mma_bf16(acc[mt][2 + 1], ah[mt], bh1 + 2);
#pragma unroll
            for (int mt = 0; mt < 4; mt++) mma_bf16(acc[mt][2 + 0], ah[mt], bl1 + 0);
#pragma unroll
            for (int mt = 0; mt < 4; mt++) mma_bf16(acc[mt][2 + 1], ah[mt], bl1 + 2);
#pragma unroll
            for (int mt = 0; mt < 4; mt++) mma_bf16(acc[mt][2 + 0], al[mt], bh1 + 0);
#pragma unroll
            for (int mt = 0; mt < 4; mt++) mma_bf16(acc[mt][2 + 1], al[mt], bh1 + 2);
        }
    }
    CP_WAIT0();

    // ---------------- epilogue ----------------
    const int r0 = lane >> 2;
    const int c0 = (lane & 3) * 2;
#pragma unroll
    for (int mt = 0; mt < 4; mt++) {
#pragma unroll
        for (int half = 0; half < 2; half++) {
            const int m = blockM + wm + mt * 16 + r0 + half * 8;
            const size_t base = (size_t)m * N;
#pragma unroll
            for (int nt = 0; nt < 4; nt++) {
                const int n = blockN + wn + nt * 8 + c0;
                float v0 = acc[mt][nt][half * 2 + 0];
                float v1 = acc[mt][nt][half * 2 + 1];
                float b0 = 0.f, b1 = 0.f, h0 = 0.f, h1 = 0.f, rr0 = 0.f, rr1 = 0.f;
                if (OP != OP_NONE) { b0 = bias[n]; b1 = bias[n + 1]; }
                if (OP == OP_GATE) {
                    float2 hh = *(const float2*)(Hm + base + n);
                    float2 rr = *(const float2*)(Rm + base + n);
                    h0 = hh.x; h1 = hh.y; rr0 = rr.x; rr1 = rr.y;
                }
                v0 = epi_op<OP>(v0, b0, h0, rr0);
                v1 = epi_op<OP>(v1, b1, h1, rr1);
                if (WF32) *(float2*)(CF + base + n) = make_float2(v0, v1);
                if (WSPLIT) {
                    __nv_bfloat16 hA, lA, hB, lB;
                    split_bf16(v0, hA, lA);
                    split_bf16(v1, hB, lB);
                    __nv_bfloat162 ph; ph.x = hA; ph.y = hB;
                    __nv_bfloat162 pl; pl.x = lA; pl.y = lB;
                    *(__nv_bfloat162*)(CH + base + n) = ph;
                    *(__nv_bfloat162*)(CL + base + n) = pl;
                }
            }
        }
    }
}

// ------------------------- launch ------------------------------------------
extern "C" void kernel_launch(void* const* d_in, const int* in_sizes, int n_in,
                              void* d_out, int out_size)
{
    const float* x      = (const float*)d_in[0];
    const float* preG   = (const float*)d_in[1];
    const float* preB   = (const float*)d_in[2];
    const float* preDw  = (const float*)d_in[3];
    const float* preDb  = (const float*)d_in[4];
    const float* preGw  = (const float*)d_in[5];
    const float* preGb  = (const float*)d_in[6];
    const float* core0  = (const float*)d_in[7];
    const float* core1  = (const float*)d_in[8];
    const float* core2  = (const float*)d_in[9];
    const float* postG  = (const float*)d_in[10];
    const float* postB  = (const float*)d_in[11];
    const float* postDw = (const float*)d_in[12];
    const float* postDb = (const float*)d_in[13];
    const float* postGw = (const float*)d_in[14];
    const float* postGb = (const float*)d_in[15];
    float* out = (float*)d_out;

    float *h1, *t, *h2, *a01;
    cudaGetSymbolAddress((void**)&h1,  g_h1);
    cudaGetSymbolAddress((void**)&t,   g_t);
    cudaGetSymbolAddress((void**)&h2,  g_h2);
    cudaGetSymbolAddress((void**)&a01, g_a01);

    __nv_bfloat16 *xH, *xL, *ln1H, *ln1L, *hpreH, *hpreL, *tH, *tL, *ln2H, *ln2L;
    __nv_bfloat16 *preDwTH, *preDwTL, *preGwTH, *preGwTL;
    __nv_bfloat16 *wttTH, *wttTL, *postDwTH, *postDwTL, *postGwTH, *postGwTL;
    cudaGetSymbolAddress((void**)&xH,    g_xH);    cudaGetSymbolAddress((void**)&xL,    g_xL);
    cudaGetSymbolAddress((void**)&ln1H,  g_ln1H);  cudaGetSymbolAddress((void**)&ln1L,  g_ln1L);
    cudaGetSymbolAddress((void**)&hpreH, g_hpreH); cudaGetSymbolAddress((void**)&hpreL, g_hpreL);
    cudaGetSymbolAddress((void**)&tH,    g_tH);    cudaGetSymbolAddress((void**)&tL,    g_tL);
    cudaGetSymbolAddress((void**)&ln2H,  g_ln2H);  cudaGetSymbolAddress((void**)&ln2L,  g_ln2L);
    cudaGetSymbolAddress((void**)&preDwTH,  g_preDwTH);  cudaGetSymbolAddress((void**)&preDwTL,  g_preDwTL);
    cudaGetSymbolAddress((void**)&preGwTH,  g_preGwTH);  cudaGetSymbolAddress((void**)&preGwTL,  g_preGwTL);
    cudaGetSymbolAddress((void**)&wttTH,    g_wttTH);    cudaGetSymbolAddress((void**)&wttTL,    g_wttTL);
    cudaGetSymbolAddress((void**)&postDwTH, g_postDwTH); cudaGetSymbolAddress((void**)&postDwTL, g_postDwTL);
    cudaGetSymbolAddress((void**)&postGwTH, g_postGwTH); cudaGetSymbolAddress((void**)&postGwTL, g_postGwTL);

    cudaFuncSetAttribute(mma_gemm_kernel<OP_GELU, true, false>,
                         cudaFuncAttributeMaxDynamicSharedMemorySize, GEMM_SMEM);
    cudaFuncSetAttribute(mma_gemm_kernel<OP_GATE, false, true>,
                         cudaFuncAttributeMaxDynamicSharedMemorySize, GEMM_SMEM);
    cudaFuncSetAttribute(mma_gemm_kernel<OP_NONE, true, true>,
                         cudaFuncAttributeMaxDynamicSharedMemorySize, GEMM_SMEM);
    cudaFuncSetAttribute(mma_gemm_kernel<OP_GATE, true, false>,
                         cudaFuncAttributeMaxDynamicSharedMemorySize, GEMM_SMEM);

    // --- operator prep (independent of x) ---
    build_a01_kernel<<<131072 / 256, 256>>>(core0, core1, a01);
    build_wttT_kernel<<<(DIN * DOUT) / 256, 256>>>(a01, core2, wttTH, wttTL);
    transpose_split_kernel<<<dim3(DIN / 32, DIN / 32), 256>>>(preDw, preDwTH, preDwTL, DIN, DIN);
    transpose_split_kernel<<<dim3(DIN / 32, DIN / 32), 256>>>(preGw, preGwTH, preGwTL, DIN, DIN);
    transpose_split_kernel<<<dim3(DOUT / 32, DOUT / 32), 256>>>(postDw, postDwTH, postDwTL, DOUT, DOUT);
    transpose_split_kernel<<<dim3(DOUT / 32, DOUT / 32), 256>>>(postGw, postGwTH, postGwTL, DOUT, DOUT);

    // --- pre block ---
    layernorm_split_kernel<DIN / 256, true><<<NTOK, 256>>>(
        x, preG, preB, ln1H, ln1L, xH, xL, DIN);
    mma_gemm_kernel<OP_GELU, true, false><<<dim3(NTOK / BM, DIN / BN), 256, GEMM_SMEM>>>(
        ln1H, ln1L, preDwTH, preDwTL, preDb, nullptr, nullptr,
        h1, nullptr, nullptr, NTOK, DIN, DIN);
    mma_gemm_kernel<OP_GATE, false, true><<<dim3(NTOK / BM, DIN / BN), 256, GEMM_SMEM>>>(
        xH, xL, preGwTH, preGwTL, preGb, h1, x,
        nullptr, hpreH, hpreL, NTOK, DIN, DIN);

    // --- TT contraction ---
    mma_gemm_kernel<OP_NONE, true, true><<<dim3(NTOK / BM, DOUT / BN), 256, GEMM_SMEM>>>(
        hpreH, hpreL, wttTH, wttTL, nullptr, nullptr, nullptr,
        t, tH, tL, NTOK, DOUT, DIN);

    // --- post block ---
    layernorm_split_kernel<DOUT / 256, false><<<NTOK, 256>>>(
        t, postG, postB, ln2H, ln2L, nullptr, nullptr, DOUT);
    mma_gemm_kernel<OP_GELU, true, false><<<dim3(NTOK / BM, DOUT / BN), 256, GEMM_SMEM>>>(
        ln2H, ln2L, postDwTH, postDwTL, postDb, nullptr, nullptr,
        h2, nullptr, nullptr, NTOK, DOUT, DOUT);
    mma_gemm_kernel<OP_GATE, true, false><<<dim3(NTOK / BM, DOUT / BN), 256, GEMM_SMEM>>>(
        tH, tL, postGwTH, postGwTL, postGb, h2, t,
        out, nullptr, nullptr, NTOK, DOUT, DOUT);
}